// round 15
// baseline (speedup 1.0000x reference)
#include <cuda_runtime.h>
#include <cuda_fp16.h>
#include <cstdint>
#include <math.h>

// Problem constants
#define NTOK 2048
#define HID 2048
#define NH 32
#define NKV 8
#define HD 64
#define NE 4
#define CHUNK (NTOK / NE)   // 512
#define DQ (NH * HD)        // 2048
#define DKV (NKV * HD)      // 512

typedef __half fp16;

// Scratch (single fp16 everywhere)
__device__ fp16 g_h[(size_t)NTOK * HID];
__device__ fp16 g_o[(size_t)NTOK * DQ];
__device__ fp16 g_qv[(size_t)NTOK * DQ];
__device__ fp16 g_kv[(size_t)NTOK * DKV];
__device__ fp16 g_vv[(size_t)NTOK * DKV];

__device__ fp16 g_wq[(size_t)NE * HID * DQ];   // [K][N] original layout
__device__ fp16 g_wo[(size_t)NE * DQ * HID];
__device__ fp16 g_wk[(size_t)HID * DKV];
__device__ fp16 g_wv[(size_t)HID * DKV];

__device__ float2 g_rope[(size_t)NTOK * 32];

// ---------------------------------------------------------------------------
__device__ __forceinline__ uint32_t smem_u32(const void* p) {
    uint32_t a;
    asm("{ .reg .u64 t; cvta.to.shared.u64 t, %1; cvt.u32.u64 %0, t; }"
        : "=r"(a) : "l"(p));
    return a;
}

#define CP16(dst, src) \
    asm volatile("cp.async.cg.shared.global [%0], [%1], 16;" \
        :: "r"(dst), "l"(src) : "memory")
#define CP_COMMIT() asm volatile("cp.async.commit_group;" ::: "memory")
#define CP_WAIT(n) asm volatile("cp.async.wait_group %0;" :: "n"(n) : "memory")

#define MMA16816(d, a, b0, b1) \
    asm volatile("mma.sync.aligned.m16n8k16.row.col.f32.f16.f16.f32 " \
        "{%0,%1,%2,%3}, {%4,%5,%6,%7}, {%8,%9}, {%0,%1,%2,%3};" \
        : "+f"((d)[0]), "+f"((d)[1]), "+f"((d)[2]), "+f"((d)[3]) \
        : "r"((a)[0]), "r"((a)[1]), "r"((a)[2]), "r"((a)[3]), "r"(b0), "r"(b1))

#define LDSM_4(r0, r1, r2, r3, a) \
    asm volatile("ldmatrix.sync.aligned.m8n8.x4.shared.b16 {%0,%1,%2,%3}, [%4];" \
        : "=r"(r0), "=r"(r1), "=r"(r2), "=r"(r3) : "r"(a))

#define LDSM_T4(r0, r1, r2, r3, a) \
    asm volatile("ldmatrix.sync.aligned.m8n8.x4.trans.shared.b16 {%0,%1,%2,%3}, [%4];" \
        : "=r"(r0), "=r"(r1), "=r"(r2), "=r"(r3) : "r"(a))

#define REDV2(addr, a, b) \
    asm volatile("red.global.add.v2.f32 [%0], {%1, %2};" \
        :: "l"(addr), "f"(a), "f"(b) : "memory")

__device__ __forceinline__ uint32_t pack_half2(float a, float b) {
    __half2 h = __floats2half2_rn(a, b);
    return *reinterpret_cast<uint32_t*>(&h);
}

// ---------------------------------------------------------------------------
// Prep: coalesced fp32->fp16 converts (8 floats/thread) + RoPE table.
// ---------------------------------------------------------------------------
__device__ __forceinline__ void conv8(const float* __restrict__ X,
                                      fp16* __restrict__ H, int i) {
    float4 v0 = reinterpret_cast<const float4*>(X)[2 * i];
    float4 v1 = reinterpret_cast<const float4*>(X)[2 * i + 1];
    uint4 o;
    o.x = pack_half2(v0.x, v0.y);
    o.y = pack_half2(v0.z, v0.w);
    o.z = pack_half2(v1.x, v1.y);
    o.w = pack_half2(v1.z, v1.w);
    reinterpret_cast<uint4*>(H)[i] = o;
}

#define PB_Q 8192
#define PB_O 8192
#define PB_K 512
#define PB_V 512
#define PB_H 2048
#define PB_R 256
#define PREP_BLOCKS (PB_Q + PB_O + PB_K + PB_V + PB_H + PB_R)

__global__ void __launch_bounds__(256) prep_split(
    const float* __restrict__ q_proj_w, const float* __restrict__ o_proj_w,
    const float* __restrict__ k_w, const float* __restrict__ v_w,
    const float* __restrict__ hidden, const int* __restrict__ pos,
    fp16* __restrict__ wq, fp16* __restrict__ wo,
    fp16* __restrict__ wk, fp16* __restrict__ wv,
    fp16* __restrict__ h, float2* __restrict__ rope)
{
    int b = blockIdx.x;
    int tid = threadIdx.x;
    if (b < PB_Q) {
        conv8(q_proj_w, wq, b * 256 + tid);
    } else if (b < PB_Q + PB_O) {
        conv8(o_proj_w, wo, (b - PB_Q) * 256 + tid);
    } else if (b < PB_Q + PB_O + PB_K) {
        conv8(k_w, wk, (b - PB_Q - PB_O) * 256 + tid);
    } else if (b < PB_Q + PB_O + PB_K + PB_V) {
        conv8(v_w, wv, (b - PB_Q - PB_O - PB_K) * 256 + tid);
    } else if (b < PB_Q + PB_O + PB_K + PB_V + PB_H) {
        conv8(hidden, h, (b - PB_Q - PB_O - PB_K - PB_V) * 256 + tid);
    } else {
        int i = (b - PB_Q - PB_O - PB_K - PB_V - PB_H) * 256 + tid;
        int t = i >> 5;
        int c = i & 31;
        float inv = powf(10000.0f, -(float)c * (1.0f / 32.0f));
        float s, cs;
        sincosf((float)pos[t] * inv, &s, &cs);
        rope[i] = make_float2(cs, s);
    }
}

// ---------------------------------------------------------------------------
// fp16 mma.sync GEMM (128x128 CTA tile, 128 threads, 4 warps of 64x64).
// 3-slot cp.async pipeline, one barrier per k-iteration.
// B from [K][N] via ldmatrix.trans. Supports split-K via (kb0, Ksp).
// ---------------------------------------------------------------------------
#define LDA 40
#define LDB 136
#define A_E (128 * LDA)                // 5120 elements
#define B_E (32 * LDB)                 // 4352 elements
#define STAGE_EL (A_E + B_E)           // 9472 el = 18944 B
#define NSTG 3
#define GEMM_SMEM (1024 + NSTG * STAGE_EL * 2)   // 57856

__device__ __forceinline__ void issue_tile(
    uint32_t sB, int s, int kb,
    const fp16* __restrict__ Ag, const fp16* __restrict__ Bg,
    const int* __restrict__ rows, int n0, int Kst, int Nd, int tid)
{
#pragma unroll
    for (int rep = 0; rep < 4; rep++) {
        int f = tid + rep * 128;               // 0..511
        int m = f >> 2;
        int q = f & 3;
        uint32_t adst = sB + (uint32_t)s * (STAGE_EL * 2) + m * (LDA * 2) + q * 16;
        CP16(adst, Ag + (size_t)rows[m] * Kst + kb + q * 8);
        int kk = f >> 4;
        int seg = f & 15;
        uint32_t bdst = sB + (uint32_t)s * (STAGE_EL * 2) + (A_E + kk * LDB) * 2
                      + seg * 16;
        CP16(bdst, Bg + (size_t)(kb + kk) * Nd + n0 + seg * 8);
    }
}

__device__ __forceinline__ void gemm_mainloop(
    const fp16* __restrict__ Ag, const fp16* __restrict__ Bg,
    const int* __restrict__ idx,
    int Kst, int Ksp, int kb0, int Nd, int m0, int n0, int zchunk, char* smc,
    float acc[4][8][4])
{
    int* rows = (int*)smc;
    const uint32_t sB = smem_u32(smc + 1024);
    const int tid = threadIdx.x;
    const int wid = tid >> 5;
    const int lane = tid & 31;

    {
        int lr = zchunk + m0 + tid;
        rows[tid] = idx ? idx[lr] : lr;
    }
    __syncthreads();

    const int wm = (wid & 1) * 64;
    const int wn = (wid >> 1) * 64;
    const uint32_t lnA = ((((lane >> 3) & 1) * 8 + (lane & 7)) * LDA + (lane >> 4) * 8) * 2;
    const uint32_t lnBT = ((lane & 15) * LDB + (lane >> 4) * 8) * 2;

#pragma unroll
    for (int a = 0; a < 4; a++)
#pragma unroll
        for (int b = 0; b < 8; b++)
#pragma unroll
            for (int c = 0; c < 4; c++) acc[a][b][c] = 0.f;

    const int nkt = Ksp / 32;
    issue_tile(sB, 0, kb0, Ag, Bg, rows, n0, Kst, Nd, tid); CP_COMMIT();
    issue_tile(sB, 1, kb0 + 32, Ag, Bg, rows, n0, Kst, Nd, tid); CP_COMMIT();

    int s = 0;
    for (int kt = 0; kt < nkt; kt++) {
        if (kt < nkt - 1) CP_WAIT(1);
        else              CP_WAIT(0);
        __syncthreads();

        if (kt + 2 < nkt) {
            int s2 = (s + 2 >= NSTG) ? s + 2 - NSTG : s + 2;
            issue_tile(sB, s2, kb0 + (kt + 2) * 32, Ag, Bg, rows, n0, Kst, Nd, tid);
            CP_COMMIT();
        }

        const uint32_t sb_s = sB + (uint32_t)s * (STAGE_EL * 2);
        const uint32_t bb_s = sb_s + (uint32_t)A_E * 2;

#pragma unroll
        for (int ks = 0; ks < 32; ks += 16) {
            uint32_t ah[4][4];
            uint32_t abase = sb_s + (uint32_t)(wm * LDA + ks) * 2 + lnA;
#pragma unroll
            for (int mi = 0; mi < 4; mi++)
                LDSM_4(ah[mi][0], ah[mi][1], ah[mi][2], ah[mi][3],
                       abase + mi * (16 * LDA * 2));
#pragma unroll
            for (int np = 0; np < 4; np++) {
                uint32_t boff = bb_s + (uint32_t)(ks * LDB + wn + np * 16) * 2 + lnBT;
                uint32_t b0, b1, b2, b3;
                LDSM_T4(b0, b1, b2, b3, boff);
#pragma unroll
                for (int mi = 0; mi < 4; mi++) {
                    MMA16816(acc[mi][2 * np], ah[mi], b0, b1);
                    MMA16816(acc[mi][2 * np + 1], ah[mi], b2, b3);
                }
            }
        }
        s = (s + 1 == NSTG) ? 0 : s + 1;
    }
}

// Epilogue: fused RMSNorm + NeoX RoPE (table) + fp16 convert (warp owns 64 cols = 1 head)
__device__ __forceinline__ void epi_norm_rope(
    float acc[4][8][4], const int* __restrict__ rows,
    const float* __restrict__ w, const float2* __restrict__ rope, float sc,
    fp16* __restrict__ Out, int outstride, int headcol0)
{
    const int lane = threadIdx.x & 31;
    const int wid = threadIdx.x >> 5;
    const int wm = (wid & 1) * 64;
    const int rq = lane >> 2, cq = lane & 3;

#pragma unroll
    for (int mi = 0; mi < 4; mi++) {
#pragma unroll
        for (int hf = 0; hf < 2; hf++) {
            int r = wm + mi * 16 + rq + hf * 8;
            int gr = rows[r];
            float ss = 0.f;
#pragma unroll
            for (int nf = 0; nf < 8; nf++) {
                float a = acc[mi][nf][hf * 2], b = acc[mi][nf][hf * 2 + 1];
                ss += a * a + b * b;
            }
            ss += __shfl_xor_sync(0xffffffff, ss, 1);
            ss += __shfl_xor_sync(0xffffffff, ss, 2);
            float rn = rsqrtf(ss * (1.0f / 64.0f) + 1e-6f) * sc;
            const float2* rt = rope + (size_t)gr * 32;
#pragma unroll
            for (int nf = 0; nf < 4; nf++) {
                float o1[2], o2[2];
#pragma unroll
                for (int par = 0; par < 2; par++) {
                    int c = nf * 8 + cq * 2 + par;
                    float y1 = acc[mi][nf][hf * 2 + par] * rn * w[c];
                    float y2 = acc[mi][nf + 4][hf * 2 + par] * rn * w[c + 32];
                    float2 cs = rt[c];
                    o1[par] = y1 * cs.x - y2 * cs.y;
                    o2[par] = y2 * cs.x + y1 * cs.y;
                }
                size_t base = (size_t)gr * outstride + headcol0 + nf * 8 + cq * 2;
                *reinterpret_cast<uint32_t*>(Out + base) = pack_half2(o1[0], o1[1]);
                *reinterpret_cast<uint32_t*>(Out + base + 32) = pack_half2(o2[0], o2[1]);
            }
        }
    }
}

// Epilogue: plain fp16 convert (v)
__device__ __forceinline__ void epi_conv(
    float acc[4][8][4], const int* __restrict__ rows,
    fp16* __restrict__ Out, int outstride, int col0)
{
    const int lane = threadIdx.x & 31;
    const int wid = threadIdx.x >> 5;
    const int wm = (wid & 1) * 64;
    const int wn = (wid >> 1) * 64;
    const int rq = lane >> 2, cq = lane & 3;
#pragma unroll
    for (int mi = 0; mi < 4; mi++) {
        int r = wm + mi * 16 + rq;
        size_t gr0 = (size_t)rows[r];
        size_t gr1 = (size_t)rows[r + 8];
#pragma unroll
        for (int nf = 0; nf < 8; nf++) {
            int col = col0 + wn + nf * 8 + cq * 2;
            *reinterpret_cast<uint32_t*>(Out + gr0 * outstride + col) =
                pack_half2(acc[mi][nf][0], acc[mi][nf][1]);
            *reinterpret_cast<uint32_t*>(Out + gr1 * outstride + col) =
                pack_half2(acc[mi][nf][2], acc[mi][nf][3]);
        }
    }
}

// Merged q-proj (bid<256, routed) + k-proj + v-proj; fused norm/rope epilogues.
__global__ void __launch_bounds__(128, 3) gemm_qkv(
    const fp16* __restrict__ h, const fp16* __restrict__ wq,
    const fp16* __restrict__ wk, const fp16* __restrict__ wv,
    const int* __restrict__ sort_idx, const float2* __restrict__ rope,
    const float* __restrict__ q_norm_w, const float* __restrict__ k_norm_w,
    fp16* __restrict__ qv, fp16* __restrict__ kv, fp16* __restrict__ vv)
{
    extern __shared__ char smc[];
    float acc[4][8][4];
    int* rows = (int*)smc;
    int bid = blockIdx.x;
    const int wn = ((threadIdx.x >> 5) >> 1) * 64;

    if (bid < 256) {
        int x = bid & 15, y = (bid >> 4) & 3, z = bid >> 6;
        gemm_mainloop(h, wq + (size_t)z * HID * DQ,
                      sort_idx, HID, HID, 0, DQ, y * 128, x * 128, z * CHUNK, smc, acc);
        epi_norm_rope(acc, rows, q_norm_w, rope, 0.125f, qv, DQ, x * 128 + wn);
    } else {
        int bb = bid - 256;
        int x = bb & 7, y = bb >> 3;
        if (x < 4) {
            gemm_mainloop(h, wk, nullptr, HID, HID, 0, DKV, y * 128, x * 128, 0, smc, acc);
            epi_norm_rope(acc, rows, k_norm_w, rope, 1.0f, kv, DKV, x * 128 + wn);
        } else {
            gemm_mainloop(h, wv, nullptr, HID, HID, 0, DKV, y * 128, (x - 4) * 128, 0, smc, acc);
            epi_conv(acc, rows, vv, DKV, (x - 4) * 128);
        }
    }
}

// o-proj (routed), split-K=2, fp32 red-atomic output into zeroed buffer.
__global__ void __launch_bounds__(128, 3) gemm_o(
    const fp16* __restrict__ o, const fp16* __restrict__ wo,
    float* __restrict__ out, const int* __restrict__ sort_idx)
{
    extern __shared__ char smc[];
    float acc[4][8][4];
    int* rows = (int*)smc;
    int bid = blockIdx.x;
    int ksl = bid >> 8;                  // 0 or 1
    int bb = bid & 255;
    int x = bb & 15, y = (bb >> 4) & 3, z = bb >> 6;
    gemm_mainloop(o, wo + (size_t)z * DQ * HID,
                  sort_idx, DQ, DQ / 2, ksl * (DQ / 2), HID,
                  y * 128, x * 128, z * CHUNK, smc, acc);

    const int lane = threadIdx.x & 31;
    const int wid = threadIdx.x >> 5;
    const int wm = (wid & 1) * 64;
    const int wn = (wid >> 1) * 64;
    const int rq = lane >> 2;
    const int cq = (lane & 3) * 2;
#pragma unroll
    for (int mi = 0; mi < 4; mi++) {
        int r = wm + mi * 16 + rq;
        size_t gr0 = (size_t)rows[r];
        size_t gr1 = (size_t)rows[r + 8];
#pragma unroll
        for (int ni = 0; ni < 8; ni++) {
            int col = x * 128 + wn + ni * 8 + cq;
            REDV2(&out[gr0 * HID + col], acc[mi][ni][0], acc[mi][ni][1]);
            REDV2(&out[gr1 * HID + col], acc[mi][ni][2], acc[mi][ni][3]);
        }
    }
}

// ---------------------------------------------------------------------------
// fp16 flash attention, AQ=64 / 128 threads / 3 CTAs per SM.
// 3-slot KV pipeline, ONE barrier per tile iteration.
// ---------------------------------------------------------------------------
#define AQ 64
#define AK 64
#define LDK 72
#define KSM (AK * LDK)     // 4608 elements
#define ASTG 3
#define ASMEM (2 * ASTG * KSM * 2 + ASTG * AK * 4)   // 56064

__device__ __forceinline__ void attn_issue(
    uint32_t sbase, int s, int kt, int kvh, int tid,
    const fp16* __restrict__ k_g, const fp16* __restrict__ v_g,
    const int* __restrict__ pos, int* __restrict__ kpos_sm)
{
#pragma unroll
    for (int i = 0; i < 8; i++) {
        int f = tid + i * 128;          // 0..1023
        int arr = f >> 9;               // 0=K, 1=V
        int r = (f >> 3) & 63;
        int seg = f & 7;
        const fp16* src = arr ? v_g : k_g;
        uint32_t dst = sbase + (uint32_t)((s * 2 + arr) * KSM + r * LDK) * 2
                     + seg * 16;
        CP16(dst, src + (size_t)(kt * AK + r) * DKV + (size_t)kvh * HD + seg * 8);
    }
    if (tid < AK) kpos_sm[s * AK + tid] = pos[kt * AK + tid];
    CP_COMMIT();
}

__global__ void __launch_bounds__(128, 3) attn_mma(
    const fp16* __restrict__ q_g, const fp16* __restrict__ k_g,
    const fp16* __restrict__ v_g, const int* __restrict__ pos,
    fp16* __restrict__ o_g)
{
    extern __shared__ char sm[];
    const uint32_t sbase = smem_u32(sm);
    int* kpos = (int*)(sm + (size_t)2 * ASTG * KSM * 2);

    const int tid = threadIdx.x;
    const int w = tid >> 5;
    const int l = tid & 31;
    const int qt = gridDim.x - 1 - blockIdx.x;   // heavy tiles first
    const int h = blockIdx.y;
    const int kvh = h >> 2;
    const int q0 = qt * AQ;
    const int ntile = qt + 1;

    attn_issue(sbase, 0, 0, kvh, tid, k_g, v_g, pos, kpos);
    attn_issue(sbase, 1, 1 < ntile ? 1 : 0, kvh, tid, k_g, v_g, pos, kpos);

    const int rq = l >> 2;
    const int cq = l & 3;
    const int row0 = w * 16 + rq;

    uint32_t qf[4][4];
    {
        const fp16* qb = q_g + (size_t)(q0 + row0) * DQ + h * HD;
#pragma unroll
        for (int kf = 0; kf < 4; kf++) {
            int e0 = kf * 16 + cq * 2;
            qf[kf][0] = *reinterpret_cast<const uint32_t*>(qb + e0);
            qf[kf][1] = *reinterpret_cast<const uint32_t*>(qb + 8 * DQ + e0);
            qf[kf][2] = *reinterpret_cast<const uint32_t*>(qb + e0 + 8);
            qf[kf][3] = *reinterpret_cast<const uint32_t*>(qb + 8 * DQ + e0 + 8);
        }
    }
    const int qp0 = pos[q0 + row0];
    const int qp1 = pos[q0 + row0 + 8];

    float o[8][4];
#pragma unroll
    for (int nf = 0; nf < 8; nf++)
#pragma unroll
        for (int e = 0; e < 4; e++) o[nf][e] = 0.f;
    float m0 = -1e30f, m1 = -1e30f, l0 = 0.f, l1 = 0.f;

    const int lrow16 = l & 15;
    const int lsel = l >> 4;
    const uint32_t lnK = (((l >> 4) * 8 + (l & 7)) * LDK + ((l >> 3) & 1) * 8) * 2;

    int s = 0;
    for (int kt = 0; kt < ntile; kt++) {
        if (kt < ntile - 1) CP_WAIT(1);
        else                CP_WAIT(0);
        __syncthreads();

        if (kt + 2 < ntile) {
            int s2 = (s + 2 >= ASTG) ? s + 2 - ASTG : s + 2;
            attn_issue(sbase, s2, kt + 2, kvh, tid, k_g, v_g, pos, kpos);
        }

        const uint32_t kb = sbase + (uint32_t)((s * 2 + 0) * KSM) * 2;
        const uint32_t vb = sbase + (uint32_t)((s * 2 + 1) * KSM) * 2;

        float sv[8][4];
#pragma unroll
        for (int nf = 0; nf < 8; nf++)
#pragma unroll
            for (int e = 0; e < 4; e++) sv[nf][e] = 0.f;

#pragma unroll
        for (int kf = 0; kf < 4; kf++) {
#pragma unroll
            for (int np = 0; np < 4; np++) {
                uint32_t koff = kb + (uint32_t)(np * 16 * LDK) * 2 + kf * 32 + lnK;
                uint32_t b0, b1, b2, b3;
                LDSM_4(b0, b1, b2, b3, koff);
                MMA16816(sv[2 * np], qf[kf], b0, b1);
                MMA16816(sv[2 * np + 1], qf[kf], b2, b3);
            }
        }

        if (kt == qt) {
            const int* kp = kpos + s * AK;
#pragma unroll
            for (int nf = 0; nf < 8; nf++) {
                int c = nf * 8 + cq * 2;
                int k0 = kp[c], k1 = kp[c + 1];
                if (k0 > qp0) sv[nf][0] = -1e30f;
                if (k1 > qp0) sv[nf][1] = -1e30f;
                if (k0 > qp1) sv[nf][2] = -1e30f;
                if (k1 > qp1) sv[nf][3] = -1e30f;
            }
        }

        float mt0 = -1e30f, mt1 = -1e30f;
#pragma unroll
        for (int nf = 0; nf < 8; nf++) {
            mt0 = fmaxf(mt0, fmaxf(sv[nf][0], sv[nf][1]));
            mt1 = fmaxf(mt1, fmaxf(sv[nf][2], sv[nf][3]));
        }
        mt0 = fmaxf(mt0, __shfl_xor_sync(0xffffffff, mt0, 1));
        mt0 = fmaxf(mt0, __shfl_xor_sync(0xffffffff, mt0, 2));
        mt1 = fmaxf(mt1, __shfl_xor_sync(0xffffffff, mt1, 1));
        mt1 = fmaxf(mt1, __shfl_xor_sync(0xffffffff, mt1, 2));
        float mn0 = fmaxf(m0, mt0), mn1 = fmaxf(m1, mt1);
        float a0 = __expf(m0 - mn0), a1 = __expf(m1 - mn1);
        m0 = mn0; m1 = mn1;
#pragma unroll
        for (int nf = 0; nf < 8; nf++) {
            o[nf][0] *= a0; o[nf][1] *= a0;
            o[nf][2] *= a1; o[nf][3] *= a1;
        }
        float rs0 = 0.f, rs1 = 0.f;
#pragma unroll
        for (int nf = 0; nf < 8; nf++) {
            sv[nf][0] = __expf(sv[nf][0] - mn0); rs0 += sv[nf][0];
            sv[nf][1] = __expf(sv[nf][1] - mn0); rs0 += sv[nf][1];
            sv[nf][2] = __expf(sv[nf][2] - mn1); rs1 += sv[nf][2];
            sv[nf][3] = __expf(sv[nf][3] - mn1); rs1 += sv[nf][3];
        }
        rs0 += __shfl_xor_sync(0xffffffff, rs0, 1);
        rs0 += __shfl_xor_sync(0xffffffff, rs0, 2);
        rs1 += __shfl_xor_sync(0xffffffff, rs1, 1);
        rs1 += __shfl_xor_sync(0xffffffff, rs1, 2);
        l0 = l0 * a0 + rs0;
        l1 = l1 * a1 + rs1;

#pragma unroll
        for (int kfk = 0; kfk < 4; kfk++) {
            uint32_t pa[4];
            pa[0] = pack_half2(sv[2 * kfk][0], sv[2 * kfk][1]);
            pa[1] = pack_half2(sv[2 * kfk][2], sv[2 * kfk][3]);
            pa[2] = pack_half2(sv[2 * kfk + 1][0], sv[2 * kfk + 1][1]);
            pa[3] = pack_half2(sv[2 * kfk + 1][2], sv[2 * kfk + 1][3]);

            uint32_t vf[8][2];
#pragma unroll
            for (int nfp = 0; nfp < 4; nfp++) {
                uint32_t off = (uint32_t)((kfk * 16 + lrow16) * LDK
                                          + nfp * 16 + lsel * 8) * 2;
                uint32_t r0, r1, r2, r3;
                LDSM_T4(r0, r1, r2, r3, vb + off);
                vf[2 * nfp][0] = r0;     vf[2 * nfp][1] = r1;
                vf[2 * nfp + 1][0] = r2; vf[2 * nfp + 1][1] = r3;
            }
#pragma unroll
            for (int nf = 0; nf < 8; nf++)
                MMA16816(o[nf], pa, vf[nf][0], vf[nf][1]);
        }

        s = (s + 1 == ASTG) ? 0 : s + 1;
    }

    float i0 = 1.f / l0, i1 = 1.f / l1;
    int g0 = q0 + w * 16 + rq;
    int g1 = g0 + 8;
#pragma unroll
    for (int nf = 0; nf < 8; nf++) {
        int col = h * HD + nf * 8 + cq * 2;
        *reinterpret_cast<uint32_t*>(o_g + (size_t)g0 * DQ + col) =
            pack_half2(o[nf][0] * i0, o[nf][1] * i0);
        *reinterpret_cast<uint32_t*>(o_g + (size_t)g1 * DQ + col) =
            pack_half2(o[nf][2] * i1, o[nf][3] * i1);
    }
}

// ---------------------------------------------------------------------------
extern "C" void kernel_launch(void* const* d_in, const int* in_sizes, int n_in,
                              void* d_out, int out_size)
{
    const float* hidden    = (const float*)d_in[0];
    const int*   positions = (const int*)  d_in[1];
    const int*   sort_idx  = (const int*)  d_in[2];
    const float* q_proj_w  = (const float*)d_in[3];
    const float* o_proj_w  = (const float*)d_in[4];
    const float* k_w       = (const float*)d_in[5];
    const float* v_w       = (const float*)d_in[6];
    const float* q_norm_w  = (const float*)d_in[7];
    const float* k_norm_w  = (const float*)d_in[8];
    float* out = (float*)d_out;

    fp16 *h, *o, *qv, *kv, *vv, *wq, *wo, *wk, *wv;
    float2* rope;
    cudaGetSymbolAddress((void**)&h, g_h);
    cudaGetSymbolAddress((void**)&o, g_o);
    cudaGetSymbolAddress((void**)&qv, g_qv);
    cudaGetSymbolAddress((void**)&kv, g_kv);
    cudaGetSymbolAddress((void**)&vv, g_vv);
    cudaGetSymbolAddress((void**)&wq, g_wq);
    cudaGetSymbolAddress((void**)&wo, g_wo);
    cudaGetSymbolAddress((void**)&wk, g_wk);
    cudaGetSymbolAddress((void**)&wv, g_wv);
    cudaGetSymbolAddress((void**)&rope, g_rope);

    cudaFuncSetAttribute(gemm_qkv, cudaFuncAttributeMaxDynamicSharedMemorySize, GEMM_SMEM);
    cudaFuncSetAttribute(gemm_o, cudaFuncAttributeMaxDynamicSharedMemorySize, GEMM_SMEM);
    cudaFuncSetAttribute(attn_mma, cudaFuncAttributeMaxDynamicSharedMemorySize, ASMEM);

    // 0) zero the output (split-K gemm_o accumulates with red.global)
    cudaMemsetAsync(out, 0, (size_t)NTOK * HID * sizeof(float));

    // 1) coalesced fp32->fp16 converts + RoPE table
    prep_split<<<PREP_BLOCKS, 256>>>(
        q_proj_w, o_proj_w, k_w, v_w, hidden, positions,
        wq, wo, wk, wv, h, rope);

    // 2) q/k/v projections (128-thread CTAs, single wave)
    gemm_qkv<<<384, 128, GEMM_SMEM>>>(
        h, wq, wk, wv, sort_idx, rope, q_norm_w, k_norm_w, qv, kv, vv);

    // 3) flash attention
    attn_mma<<<dim3(NTOK / AQ, NH), 128, ASMEM>>>(qv, kv, vv, positions, o);

    // 4) o-proj (routed, split-K=2, red-atomic accumulate)
    gemm_o<<<512, 128, GEMM_SMEM>>>(o, wo, out, sort_idx);
}

// round 16
// speedup vs baseline: 1.0292x; 1.0292x over previous
#include <cuda_runtime.h>
#include <cuda_fp16.h>
#include <cstdint>
#include <math.h>

// Problem constants
#define NTOK 2048
#define HID 2048
#define NH 32
#define NKV 8
#define HD 64
#define NE 4
#define CHUNK (NTOK / NE)   // 512
#define DQ (NH * HD)        // 2048
#define DKV (NKV * HD)      // 512

typedef __half fp16;

// Scratch (single fp16 everywhere)
__device__ fp16 g_h[(size_t)NTOK * HID];
__device__ fp16 g_o[(size_t)NTOK * DQ];
__device__ fp16 g_qv[(size_t)NTOK * DQ];
__device__ fp16 g_kv[(size_t)NTOK * DKV];
__device__ fp16 g_vv[(size_t)NTOK * DKV];

__device__ fp16 g_wq[(size_t)NE * HID * DQ];   // [K][N] original layout
__device__ fp16 g_wo[(size_t)NE * DQ * HID];
__device__ fp16 g_wk[(size_t)HID * DKV];
__device__ fp16 g_wv[(size_t)HID * DKV];

__device__ float2 g_rope[(size_t)NTOK * 32];

// ---------------------------------------------------------------------------
__device__ __forceinline__ uint32_t smem_u32(const void* p) {
    uint32_t a;
    asm("{ .reg .u64 t; cvta.to.shared.u64 t, %1; cvt.u32.u64 %0, t; }"
        : "=r"(a) : "l"(p));
    return a;
}

#define CP16(dst, src) \
    asm volatile("cp.async.cg.shared.global [%0], [%1], 16;" \
        :: "r"(dst), "l"(src) : "memory")
#define CP_COMMIT() asm volatile("cp.async.commit_group;" ::: "memory")
#define CP_WAIT(n) asm volatile("cp.async.wait_group %0;" :: "n"(n) : "memory")

#define MMA16816(d, a, b0, b1) \
    asm volatile("mma.sync.aligned.m16n8k16.row.col.f32.f16.f16.f32 " \
        "{%0,%1,%2,%3}, {%4,%5,%6,%7}, {%8,%9}, {%0,%1,%2,%3};" \
        : "+f"((d)[0]), "+f"((d)[1]), "+f"((d)[2]), "+f"((d)[3]) \
        : "r"((a)[0]), "r"((a)[1]), "r"((a)[2]), "r"((a)[3]), "r"(b0), "r"(b1))

#define LDSM_4(r0, r1, r2, r3, a) \
    asm volatile("ldmatrix.sync.aligned.m8n8.x4.shared.b16 {%0,%1,%2,%3}, [%4];" \
        : "=r"(r0), "=r"(r1), "=r"(r2), "=r"(r3) : "r"(a))

#define LDSM_T4(r0, r1, r2, r3, a) \
    asm volatile("ldmatrix.sync.aligned.m8n8.x4.trans.shared.b16 {%0,%1,%2,%3}, [%4];" \
        : "=r"(r0), "=r"(r1), "=r"(r2), "=r"(r3) : "r"(a))

__device__ __forceinline__ uint32_t pack_half2(float a, float b) {
    __half2 h = __floats2half2_rn(a, b);
    return *reinterpret_cast<uint32_t*>(&h);
}

// ---------------------------------------------------------------------------
// Prep: coalesced fp32->fp16 converts (8 floats/thread) + RoPE table.
// ---------------------------------------------------------------------------
__device__ __forceinline__ void conv8(const float* __restrict__ X,
                                      fp16* __restrict__ H, int i) {
    float4 v0 = reinterpret_cast<const float4*>(X)[2 * i];
    float4 v1 = reinterpret_cast<const float4*>(X)[2 * i + 1];
    uint4 o;
    o.x = pack_half2(v0.x, v0.y);
    o.y = pack_half2(v0.z, v0.w);
    o.z = pack_half2(v1.x, v1.y);
    o.w = pack_half2(v1.z, v1.w);
    reinterpret_cast<uint4*>(H)[i] = o;
}

#define PB_Q 8192
#define PB_O 8192
#define PB_K 512
#define PB_V 512
#define PB_H 2048
#define PB_R 256
#define PREP_BLOCKS (PB_Q + PB_O + PB_K + PB_V + PB_H + PB_R)

__global__ void __launch_bounds__(256) prep_split(
    const float* __restrict__ q_proj_w, const float* __restrict__ o_proj_w,
    const float* __restrict__ k_w, const float* __restrict__ v_w,
    const float* __restrict__ hidden, const int* __restrict__ pos,
    fp16* __restrict__ wq, fp16* __restrict__ wo,
    fp16* __restrict__ wk, fp16* __restrict__ wv,
    fp16* __restrict__ h, float2* __restrict__ rope)
{
    int b = blockIdx.x;
    int tid = threadIdx.x;
    if (b < PB_Q) {
        conv8(q_proj_w, wq, b * 256 + tid);
    } else if (b < PB_Q + PB_O) {
        conv8(o_proj_w, wo, (b - PB_Q) * 256 + tid);
    } else if (b < PB_Q + PB_O + PB_K) {
        conv8(k_w, wk, (b - PB_Q - PB_O) * 256 + tid);
    } else if (b < PB_Q + PB_O + PB_K + PB_V) {
        conv8(v_w, wv, (b - PB_Q - PB_O - PB_K) * 256 + tid);
    } else if (b < PB_Q + PB_O + PB_K + PB_V + PB_H) {
        conv8(hidden, h, (b - PB_Q - PB_O - PB_K - PB_V) * 256 + tid);
    } else {
        int i = (b - PB_Q - PB_O - PB_K - PB_V - PB_H) * 256 + tid;
        int t = i >> 5;
        int c = i & 31;
        float inv = powf(10000.0f, -(float)c * (1.0f / 32.0f));
        float s, cs;
        sincosf((float)pos[t] * inv, &s, &cs);
        rope[i] = make_float2(cs, s);
    }
}

// ---------------------------------------------------------------------------
// fp16 mma.sync GEMM (128x128 CTA tile, 128 threads, 4 warps of 64x64).
// 3-slot cp.async pipeline, one barrier per k-iteration.
// B from [K][N] via ldmatrix.trans.
// ---------------------------------------------------------------------------
#define LDA 40
#define LDB 136
#define A_E (128 * LDA)                // 5120 elements
#define B_E (32 * LDB)                 // 4352 elements
#define STAGE_EL (A_E + B_E)           // 9472 el = 18944 B
#define NSTG 3
#define GEMM_SMEM (1024 + NSTG * STAGE_EL * 2)   // 57856

__device__ __forceinline__ void issue_tile(
    uint32_t sB, int s, int kb,
    const fp16* __restrict__ Ag, const fp16* __restrict__ Bg,
    const int* __restrict__ rows, int n0, int K, int Nd, int tid)
{
#pragma unroll
    for (int rep = 0; rep < 4; rep++) {
        int f = tid + rep * 128;               // 0..511
        int m = f >> 2;
        int q = f & 3;
        uint32_t adst = sB + (uint32_t)s * (STAGE_EL * 2) + m * (LDA * 2) + q * 16;
        CP16(adst, Ag + (size_t)rows[m] * K + kb + q * 8);
        int kk = f >> 4;
        int seg = f & 15;
        uint32_t bdst = sB + (uint32_t)s * (STAGE_EL * 2) + (A_E + kk * LDB) * 2
                      + seg * 16;
        CP16(bdst, Bg + (size_t)(kb + kk) * Nd + n0 + seg * 8);
    }
}

__device__ __forceinline__ void gemm_mainloop(
    const fp16* __restrict__ Ag, const fp16* __restrict__ Bg,
    const int* __restrict__ idx,
    int K, int Nd, int m0, int n0, int zchunk, char* smc,
    float acc[4][8][4])
{
    int* rows = (int*)smc;
    const uint32_t sB = smem_u32(smc + 1024);
    const int tid = threadIdx.x;
    const int wid = tid >> 5;
    const int lane = tid & 31;

    {
        int lr = zchunk + m0 + tid;
        rows[tid] = idx ? idx[lr] : lr;
    }
    __syncthreads();

    const int wm = (wid & 1) * 64;
    const int wn = (wid >> 1) * 64;
    const uint32_t lnA = ((((lane >> 3) & 1) * 8 + (lane & 7)) * LDA + (lane >> 4) * 8) * 2;
    const uint32_t lnBT = ((lane & 15) * LDB + (lane >> 4) * 8) * 2;

#pragma unroll
    for (int a = 0; a < 4; a++)
#pragma unroll
        for (int b = 0; b < 8; b++)
#pragma unroll
            for (int c = 0; c < 4; c++) acc[a][b][c] = 0.f;

    const int nkt = K / 32;
    issue_tile(sB, 0, 0, Ag, Bg, rows, n0, K, Nd, tid); CP_COMMIT();
    issue_tile(sB, 1, 32, Ag, Bg, rows, n0, K, Nd, tid); CP_COMMIT();

    int s = 0;
    for (int kt = 0; kt < nkt; kt++) {
        if (kt < nkt - 1) CP_WAIT(1);
        else              CP_WAIT(0);
        __syncthreads();

        if (kt + 2 < nkt) {
            int s2 = (s + 2 >= NSTG) ? s + 2 - NSTG : s + 2;
            issue_tile(sB, s2, (kt + 2) * 32, Ag, Bg, rows, n0, K, Nd, tid);
            CP_COMMIT();
        }

        const uint32_t sb_s = sB + (uint32_t)s * (STAGE_EL * 2);
        const uint32_t bb_s = sb_s + (uint32_t)A_E * 2;

#pragma unroll
        for (int ks = 0; ks < 32; ks += 16) {
            uint32_t ah[4][4];
            uint32_t abase = sb_s + (uint32_t)(wm * LDA + ks) * 2 + lnA;
#pragma unroll
            for (int mi = 0; mi < 4; mi++)
                LDSM_4(ah[mi][0], ah[mi][1], ah[mi][2], ah[mi][3],
                       abase + mi * (16 * LDA * 2));
#pragma unroll
            for (int np = 0; np < 4; np++) {
                uint32_t boff = bb_s + (uint32_t)(ks * LDB + wn + np * 16) * 2 + lnBT;
                uint32_t b0, b1, b2, b3;
                LDSM_T4(b0, b1, b2, b3, boff);
#pragma unroll
                for (int mi = 0; mi < 4; mi++) {
                    MMA16816(acc[mi][2 * np], ah[mi], b0, b1);
                    MMA16816(acc[mi][2 * np + 1], ah[mi], b2, b3);
                }
            }
        }
        s = (s + 1 == NSTG) ? 0 : s + 1;
    }
}

// Epilogue: fused RMSNorm + NeoX RoPE (table) + fp16 convert (warp owns 64 cols = 1 head)
__device__ __forceinline__ void epi_norm_rope(
    float acc[4][8][4], const int* __restrict__ rows,
    const float* __restrict__ w, const float2* __restrict__ rope, float sc,
    fp16* __restrict__ Out, int outstride, int headcol0)
{
    const int lane = threadIdx.x & 31;
    const int wid = threadIdx.x >> 5;
    const int wm = (wid & 1) * 64;
    const int rq = lane >> 2, cq = lane & 3;

#pragma unroll
    for (int mi = 0; mi < 4; mi++) {
#pragma unroll
        for (int hf = 0; hf < 2; hf++) {
            int r = wm + mi * 16 + rq + hf * 8;
            int gr = rows[r];
            float ss = 0.f;
#pragma unroll
            for (int nf = 0; nf < 8; nf++) {
                float a = acc[mi][nf][hf * 2], b = acc[mi][nf][hf * 2 + 1];
                ss += a * a + b * b;
            }
            ss += __shfl_xor_sync(0xffffffff, ss, 1);
            ss += __shfl_xor_sync(0xffffffff, ss, 2);
            float rn = rsqrtf(ss * (1.0f / 64.0f) + 1e-6f) * sc;
            const float2* rt = rope + (size_t)gr * 32;
#pragma unroll
            for (int nf = 0; nf < 4; nf++) {
                float o1[2], o2[2];
#pragma unroll
                for (int par = 0; par < 2; par++) {
                    int c = nf * 8 + cq * 2 + par;
                    float y1 = acc[mi][nf][hf * 2 + par] * rn * w[c];
                    float y2 = acc[mi][nf + 4][hf * 2 + par] * rn * w[c + 32];
                    float2 cs = rt[c];
                    o1[par] = y1 * cs.x - y2 * cs.y;
                    o2[par] = y2 * cs.x + y1 * cs.y;
                }
                size_t base = (size_t)gr * outstride + headcol0 + nf * 8 + cq * 2;
                *reinterpret_cast<uint32_t*>(Out + base) = pack_half2(o1[0], o1[1]);
                *reinterpret_cast<uint32_t*>(Out + base + 32) = pack_half2(o2[0], o2[1]);
            }
        }
    }
}

// Epilogue: plain fp16 convert (v)
__device__ __forceinline__ void epi_conv(
    float acc[4][8][4], const int* __restrict__ rows,
    fp16* __restrict__ Out, int outstride, int col0)
{
    const int lane = threadIdx.x & 31;
    const int wid = threadIdx.x >> 5;
    const int wm = (wid & 1) * 64;
    const int wn = (wid >> 1) * 64;
    const int rq = lane >> 2, cq = lane & 3;
#pragma unroll
    for (int mi = 0; mi < 4; mi++) {
        int r = wm + mi * 16 + rq;
        size_t gr0 = (size_t)rows[r];
        size_t gr1 = (size_t)rows[r + 8];
#pragma unroll
        for (int nf = 0; nf < 8; nf++) {
            int col = col0 + wn + nf * 8 + cq * 2;
            *reinterpret_cast<uint32_t*>(Out + gr0 * outstride + col) =
                pack_half2(acc[mi][nf][0], acc[mi][nf][1]);
            *reinterpret_cast<uint32_t*>(Out + gr1 * outstride + col) =
                pack_half2(acc[mi][nf][2], acc[mi][nf][3]);
        }
    }
}

// Merged q-proj (bid<256, routed) + k-proj + v-proj; fused norm/rope epilogues.
__global__ void __launch_bounds__(128, 3) gemm_qkv(
    const fp16* __restrict__ h, const fp16* __restrict__ wq,
    const fp16* __restrict__ wk, const fp16* __restrict__ wv,
    const int* __restrict__ sort_idx, const float2* __restrict__ rope,
    const float* __restrict__ q_norm_w, const float* __restrict__ k_norm_w,
    fp16* __restrict__ qv, fp16* __restrict__ kv, fp16* __restrict__ vv)
{
    extern __shared__ char smc[];
    float acc[4][8][4];
    int* rows = (int*)smc;
    int bid = blockIdx.x;
    const int wn = ((threadIdx.x >> 5) >> 1) * 64;

    if (bid < 256) {
        int x = bid & 15, y = (bid >> 4) & 3, z = bid >> 6;
        gemm_mainloop(h, wq + (size_t)z * HID * DQ,
                      sort_idx, HID, DQ, y * 128, x * 128, z * CHUNK, smc, acc);
        epi_norm_rope(acc, rows, q_norm_w, rope, 0.125f, qv, DQ, x * 128 + wn);
    } else {
        int bb = bid - 256;
        int x = bb & 7, y = bb >> 3;
        if (x < 4) {
            gemm_mainloop(h, wk, nullptr, HID, DKV, y * 128, x * 128, 0, smc, acc);
            epi_norm_rope(acc, rows, k_norm_w, rope, 1.0f, kv, DKV, x * 128 + wn);
        } else {
            gemm_mainloop(h, wv, nullptr, HID, DKV, y * 128, (x - 4) * 128, 0, smc, acc);
            epi_conv(acc, rows, vv, DKV, (x - 4) * 128);
        }
    }
}

// ---------------------------------------------------------------------------
// o-proj: 64x128 CTA tile, 64 threads (2 warps of 64x64), 512 CTAs single wave.
// ---------------------------------------------------------------------------
#define A64_E (64 * LDA)                 // 2560 elements
#define STG64_EL (A64_E + B_E)           // 6912 el = 13824 B
#define GEMM64_SMEM (1024 + NSTG * STG64_EL * 2)   // 42496

__device__ __forceinline__ void issue_tile64(
    uint32_t sB, int s, int kb,
    const fp16* __restrict__ Ag, const fp16* __restrict__ Bg,
    const int* __restrict__ rows, int n0, int K, int Nd, int tid)
{
#pragma unroll
    for (int rep = 0; rep < 12; rep++) {
        int f = tid + rep * 64;                // 0..767
        if (f < 256) {
            int m = f >> 2;
            int q = f & 3;
            uint32_t adst = sB + (uint32_t)s * (STG64_EL * 2) + m * (LDA * 2) + q * 16;
            CP16(adst, Ag + (size_t)rows[m] * K + kb + q * 8);
        } else {
            int g = f - 256;                   // 0..511
            int kk = g >> 4;
            int seg = g & 15;
            uint32_t bdst = sB + (uint32_t)s * (STG64_EL * 2) + (A64_E + kk * LDB) * 2
                          + seg * 16;
            CP16(bdst, Bg + (size_t)(kb + kk) * Nd + n0 + seg * 8);
        }
    }
}

__global__ void __launch_bounds__(64, 5) gemm_o(
    const fp16* __restrict__ o, const fp16* __restrict__ wo,
    float* __restrict__ out, const int* __restrict__ sort_idx)
{
    extern __shared__ char smc[];
    float acc[4][8][4];
    int* rows = (int*)smc;
    const uint32_t sB = smem_u32(smc + 1024);
    const int tid = threadIdx.x;
    const int wid = tid >> 5;          // 0..1
    const int lane = tid & 31;

    int bid = blockIdx.x;
    int x = bid & 15;                  // 16 N tiles
    int y = (bid >> 4) & 7;            // 8 M tiles of 64 within chunk
    int z = bid >> 7;                  // expert
    const int n0 = x * 128;
    const fp16* Bg = wo + (size_t)z * DQ * HID;

    {
        int lr = z * CHUNK + y * 64 + tid;
        rows[tid] = sort_idx[lr];
    }
    __syncthreads();

    const int wn = wid * 64;
    const uint32_t lnA = ((((lane >> 3) & 1) * 8 + (lane & 7)) * LDA + (lane >> 4) * 8) * 2;
    const uint32_t lnBT = ((lane & 15) * LDB + (lane >> 4) * 8) * 2;

#pragma unroll
    for (int a = 0; a < 4; a++)
#pragma unroll
        for (int b = 0; b < 8; b++)
#pragma unroll
            for (int c = 0; c < 4; c++) acc[a][b][c] = 0.f;

    const int nkt = DQ / 32;   // 64
    issue_tile64(sB, 0, 0, o, Bg, rows, n0, DQ, HID, tid); CP_COMMIT();
    issue_tile64(sB, 1, 32, o, Bg, rows, n0, DQ, HID, tid); CP_COMMIT();

    int s = 0;
    for (int kt = 0; kt < nkt; kt++) {
        if (kt < nkt - 1) CP_WAIT(1);
        else              CP_WAIT(0);
        __syncthreads();

        if (kt + 2 < nkt) {
            int s2 = (s + 2 >= NSTG) ? s + 2 - NSTG : s + 2;
            issue_tile64(sB, s2, (kt + 2) * 32, o, Bg, rows, n0, DQ, HID, tid);
            CP_COMMIT();
        }

        const uint32_t sb_s = sB + (uint32_t)s * (STG64_EL * 2);
        const uint32_t bb_s = sb_s + (uint32_t)A64_E * 2;

#pragma unroll
        for (int ks = 0; ks < 32; ks += 16) {
            uint32_t ah[4][4];
            uint32_t abase = sb_s + (uint32_t)ks * 2 + lnA;
#pragma unroll
            for (int mi = 0; mi < 4; mi++)
                LDSM_4(ah[mi][0], ah[mi][1], ah[mi][2], ah[mi][3],
                       abase + mi * (16 * LDA * 2));
#pragma unroll
            for (int np = 0; np < 4; np++) {
                uint32_t boff = bb_s + (uint32_t)(ks * LDB + wn + np * 16) * 2 + lnBT;
                uint32_t b0, b1, b2, b3;
                LDSM_T4(b0, b1, b2, b3, boff);
#pragma unroll
                for (int mi = 0; mi < 4; mi++) {
                    MMA16816(acc[mi][2 * np], ah[mi], b0, b1);
                    MMA16816(acc[mi][2 * np + 1], ah[mi], b2, b3);
                }
            }
        }
        s = (s + 1 == NSTG) ? 0 : s + 1;
    }

    const int rq = lane >> 2;
    const int cq = (lane & 3) * 2;
#pragma unroll
    for (int mi = 0; mi < 4; mi++) {
        int r = mi * 16 + rq;
        size_t gr0 = (size_t)rows[r];
        size_t gr1 = (size_t)rows[r + 8];
#pragma unroll
        for (int ni = 0; ni < 8; ni++) {
            int col = n0 + wn + ni * 8 + cq;
            *reinterpret_cast<float2*>(&out[gr0 * HID + col]) =
                make_float2(acc[mi][ni][0], acc[mi][ni][1]);
            *reinterpret_cast<float2*>(&out[gr1 * HID + col]) =
                make_float2(acc[mi][ni][2], acc[mi][ni][3]);
        }
    }
}

// ---------------------------------------------------------------------------
// fp16 flash attention, AQ=64 / 128 threads / 3 CTAs per SM.
// 3-slot KV pipeline, ONE barrier per tile iteration.
// ---------------------------------------------------------------------------
#define AQ 64
#define AK 64
#define LDK 72
#define KSM (AK * LDK)     // 4608 elements
#define ASTG 3
#define ASMEM (2 * ASTG * KSM * 2 + ASTG * AK * 4)   // 56064

__device__ __forceinline__ void attn_issue(
    uint32_t sbase, int s, int kt, int kvh, int tid,
    const fp16* __restrict__ k_g, const fp16* __restrict__ v_g,
    const int* __restrict__ pos, int* __restrict__ kpos_sm)
{
#pragma unroll
    for (int i = 0; i < 8; i++) {
        int f = tid + i * 128;          // 0..1023
        int arr = f >> 9;               // 0=K, 1=V
        int r = (f >> 3) & 63;
        int seg = f & 7;
        const fp16* src = arr ? v_g : k_g;
        uint32_t dst = sbase + (uint32_t)((s * 2 + arr) * KSM + r * LDK) * 2
                     + seg * 16;
        CP16(dst, src + (size_t)(kt * AK + r) * DKV + (size_t)kvh * HD + seg * 8);
    }
    if (tid < AK) kpos_sm[s * AK + tid] = pos[kt * AK + tid];
    CP_COMMIT();
}

__global__ void __launch_bounds__(128, 3) attn_mma(
    const fp16* __restrict__ q_g, const fp16* __restrict__ k_g,
    const fp16* __restrict__ v_g, const int* __restrict__ pos,
    fp16* __restrict__ o_g)
{
    extern __shared__ char sm[];
    const uint32_t sbase = smem_u32(sm);
    int* kpos = (int*)(sm + (size_t)2 * ASTG * KSM * 2);

    const int tid = threadIdx.x;
    const int w = tid >> 5;
    const int l = tid & 31;
    const int qt = gridDim.x - 1 - blockIdx.x;   // heavy tiles first
    const int h = blockIdx.y;
    const int kvh = h >> 2;
    const int q0 = qt * AQ;
    const int ntile = qt + 1;

    attn_issue(sbase, 0, 0, kvh, tid, k_g, v_g, pos, kpos);
    attn_issue(sbase, 1, 1 < ntile ? 1 : 0, kvh, tid, k_g, v_g, pos, kpos);

    const int rq = l >> 2;
    const int cq = l & 3;
    const int row0 = w * 16 + rq;

    uint32_t qf[4][4];
    {
        const fp16* qb = q_g + (size_t)(q0 + row0) * DQ + h * HD;
#pragma unroll
        for (int kf = 0; kf < 4; kf++) {
            int e0 = kf * 16 + cq * 2;
            qf[kf][0] = *reinterpret_cast<const uint32_t*>(qb + e0);
            qf[kf][1] = *reinterpret_cast<const uint32_t*>(qb + 8 * DQ + e0);
            qf[kf][2] = *reinterpret_cast<const uint32_t*>(qb + e0 + 8);
            qf[kf][3] = *reinterpret_cast<const uint32_t*>(qb + 8 * DQ + e0 + 8);
        }
    }
    const int qp0 = pos[q0 + row0];
    const int qp1 = pos[q0 + row0 + 8];

    float o[8][4];
#pragma unroll
    for (int nf = 0; nf < 8; nf++)
#pragma unroll
        for (int e = 0; e < 4; e++) o[nf][e] = 0.f;
    float m0 = -1e30f, m1 = -1e30f, l0 = 0.f, l1 = 0.f;

    const int lrow16 = l & 15;
    const int lsel = l >> 4;
    const uint32_t lnK = (((l >> 4) * 8 + (l & 7)) * LDK + ((l >> 3) & 1) * 8) * 2;

    int s = 0;
    for (int kt = 0; kt < ntile; kt++) {
        if (kt < ntile - 1) CP_WAIT(1);
        else                CP_WAIT(0);
        __syncthreads();

        if (kt + 2 < ntile) {
            int s2 = (s + 2 >= ASTG) ? s + 2 - ASTG : s + 2;
            attn_issue(sbase, s2, kt + 2, kvh, tid, k_g, v_g, pos, kpos);
        }

        const uint32_t kb = sbase + (uint32_t)((s * 2 + 0) * KSM) * 2;
        const uint32_t vb = sbase + (uint32_t)((s * 2 + 1) * KSM) * 2;

        float sv[8][4];
#pragma unroll
        for (int nf = 0; nf < 8; nf++)
#pragma unroll
            for (int e = 0; e < 4; e++) sv[nf][e] = 0.f;

#pragma unroll
        for (int kf = 0; kf < 4; kf++) {
#pragma unroll
            for (int np = 0; np < 4; np++) {
                uint32_t koff = kb + (uint32_t)(np * 16 * LDK) * 2 + kf * 32 + lnK;
                uint32_t b0, b1, b2, b3;
                LDSM_4(b0, b1, b2, b3, koff);
                MMA16816(sv[2 * np], qf[kf], b0, b1);
                MMA16816(sv[2 * np + 1], qf[kf], b2, b3);
            }
        }

        if (kt == qt) {
            const int* kp = kpos + s * AK;
#pragma unroll
            for (int nf = 0; nf < 8; nf++) {
                int c = nf * 8 + cq * 2;
                int k0 = kp[c], k1 = kp[c + 1];
                if (k0 > qp0) sv[nf][0] = -1e30f;
                if (k1 > qp0) sv[nf][1] = -1e30f;
                if (k0 > qp1) sv[nf][2] = -1e30f;
                if (k1 > qp1) sv[nf][3] = -1e30f;
            }
        }

        float mt0 = -1e30f, mt1 = -1e30f;
#pragma unroll
        for (int nf = 0; nf < 8; nf++) {
            mt0 = fmaxf(mt0, fmaxf(sv[nf][0], sv[nf][1]));
            mt1 = fmaxf(mt1, fmaxf(sv[nf][2], sv[nf][3]));
        }
        mt0 = fmaxf(mt0, __shfl_xor_sync(0xffffffff, mt0, 1));
        mt0 = fmaxf(mt0, __shfl_xor_sync(0xffffffff, mt0, 2));
        mt1 = fmaxf(mt1, __shfl_xor_sync(0xffffffff, mt1, 1));
        mt1 = fmaxf(mt1, __shfl_xor_sync(0xffffffff, mt1, 2));
        float mn0 = fmaxf(m0, mt0), mn1 = fmaxf(m1, mt1);
        float a0 = __expf(m0 - mn0), a1 = __expf(m1 - mn1);
        m0 = mn0; m1 = mn1;
#pragma unroll
        for (int nf = 0; nf < 8; nf++) {
            o[nf][0] *= a0; o[nf][1] *= a0;
            o[nf][2] *= a1; o[nf][3] *= a1;
        }
        float rs0 = 0.f, rs1 = 0.f;
#pragma unroll
        for (int nf = 0; nf < 8; nf++) {
            sv[nf][0] = __expf(sv[nf][0] - mn0); rs0 += sv[nf][0];
            sv[nf][1] = __expf(sv[nf][1] - mn0); rs0 += sv[nf][1];
            sv[nf][2] = __expf(sv[nf][2] - mn1); rs1 += sv[nf][2];
            sv[nf][3] = __expf(sv[nf][3] - mn1); rs1 += sv[nf][3];
        }
        rs0 += __shfl_xor_sync(0xffffffff, rs0, 1);
        rs0 += __shfl_xor_sync(0xffffffff, rs0, 2);
        rs1 += __shfl_xor_sync(0xffffffff, rs1, 1);
        rs1 += __shfl_xor_sync(0xffffffff, rs1, 2);
        l0 = l0 * a0 + rs0;
        l1 = l1 * a1 + rs1;

#pragma unroll
        for (int kfk = 0; kfk < 4; kfk++) {
            uint32_t pa[4];
            pa[0] = pack_half2(sv[2 * kfk][0], sv[2 * kfk][1]);
            pa[1] = pack_half2(sv[2 * kfk][2], sv[2 * kfk][3]);
            pa[2] = pack_half2(sv[2 * kfk + 1][0], sv[2 * kfk + 1][1]);
            pa[3] = pack_half2(sv[2 * kfk + 1][2], sv[2 * kfk + 1][3]);

            uint32_t vf[8][2];
#pragma unroll
            for (int nfp = 0; nfp < 4; nfp++) {
                uint32_t off = (uint32_t)((kfk * 16 + lrow16) * LDK
                                          + nfp * 16 + lsel * 8) * 2;
                uint32_t r0, r1, r2, r3;
                LDSM_T4(r0, r1, r2, r3, vb + off);
                vf[2 * nfp][0] = r0;     vf[2 * nfp][1] = r1;
                vf[2 * nfp + 1][0] = r2; vf[2 * nfp + 1][1] = r3;
            }
#pragma unroll
            for (int nf = 0; nf < 8; nf++)
                MMA16816(o[nf], pa, vf[nf][0], vf[nf][1]);
        }

        s = (s + 1 == ASTG) ? 0 : s + 1;
    }

    float i0 = 1.f / l0, i1 = 1.f / l1;
    int g0 = q0 + w * 16 + rq;
    int g1 = g0 + 8;
#pragma unroll
    for (int nf = 0; nf < 8; nf++) {
        int col = h * HD + nf * 8 + cq * 2;
        *reinterpret_cast<uint32_t*>(o_g + (size_t)g0 * DQ + col) =
            pack_half2(o[nf][0] * i0, o[nf][1] * i0);
        *reinterpret_cast<uint32_t*>(o_g + (size_t)g1 * DQ + col) =
            pack_half2(o[nf][2] * i1, o[nf][3] * i1);
    }
}

// ---------------------------------------------------------------------------
extern "C" void kernel_launch(void* const* d_in, const int* in_sizes, int n_in,
                              void* d_out, int out_size)
{
    const float* hidden    = (const float*)d_in[0];
    const int*   positions = (const int*)  d_in[1];
    const int*   sort_idx  = (const int*)  d_in[2];
    const float* q_proj_w  = (const float*)d_in[3];
    const float* o_proj_w  = (const float*)d_in[4];
    const float* k_w       = (const float*)d_in[5];
    const float* v_w       = (const float*)d_in[6];
    const float* q_norm_w  = (const float*)d_in[7];
    const float* k_norm_w  = (const float*)d_in[8];
    float* out = (float*)d_out;

    fp16 *h, *o, *qv, *kv, *vv, *wq, *wo, *wk, *wv;
    float2* rope;
    cudaGetSymbolAddress((void**)&h, g_h);
    cudaGetSymbolAddress((void**)&o, g_o);
    cudaGetSymbolAddress((void**)&qv, g_qv);
    cudaGetSymbolAddress((void**)&kv, g_kv);
    cudaGetSymbolAddress((void**)&vv, g_vv);
    cudaGetSymbolAddress((void**)&wq, g_wq);
    cudaGetSymbolAddress((void**)&wo, g_wo);
    cudaGetSymbolAddress((void**)&wk, g_wk);
    cudaGetSymbolAddress((void**)&wv, g_wv);
    cudaGetSymbolAddress((void**)&rope, g_rope);

    cudaFuncSetAttribute(gemm_qkv, cudaFuncAttributeMaxDynamicSharedMemorySize, GEMM_SMEM);
    cudaFuncSetAttribute(gemm_o, cudaFuncAttributeMaxDynamicSharedMemorySize, GEMM64_SMEM);
    cudaFuncSetAttribute(attn_mma, cudaFuncAttributeMaxDynamicSharedMemorySize, ASMEM);

    // 1) coalesced fp32->fp16 converts + RoPE table
    prep_split<<<PREP_BLOCKS, 256>>>(
        q_proj_w, o_proj_w, k_w, v_w, hidden, positions,
        wq, wo, wk, wv, h, rope);

    // 2) q/k/v projections (128-thread CTAs, single wave)
    gemm_qkv<<<384, 128, GEMM_SMEM>>>(
        h, wq, wk, wv, sort_idx, rope, q_norm_w, k_norm_w, qv, kv, vv);

    // 3) flash attention
    attn_mma<<<dim3(NTOK / AQ, NH), 128, ASMEM>>>(qv, kv, vv, positions, o);

    // 4) o-proj (64-row CTAs, 512 CTAs, single wave, no atomics)
    gemm_o<<<512, 64, GEMM64_SMEM>>>(o, wo, out, sort_idx);
}

// round 17
// speedup vs baseline: 1.1365x; 1.1043x over previous
#include <cuda_runtime.h>
#include <cuda_fp16.h>
#include <cstdint>
#include <math.h>

// Problem constants
#define NTOK 2048
#define HID 2048
#define NH 32
#define NKV 8
#define HD 64
#define NE 4
#define CHUNK (NTOK / NE)   // 512
#define DQ (NH * HD)        // 2048
#define DKV (NKV * HD)      // 512

typedef __half fp16;

// Scratch (single fp16 everywhere)
__device__ fp16 g_h[(size_t)NTOK * HID];
__device__ fp16 g_o[(size_t)NTOK * DQ];
__device__ fp16 g_qv[(size_t)NTOK * DQ];
__device__ fp16 g_kv[(size_t)NTOK * DKV];
__device__ fp16 g_vv[(size_t)NTOK * DKV];

__device__ fp16 g_wq[(size_t)NE * HID * DQ];   // [K][N] original layout
__device__ fp16 g_wo[(size_t)NE * DQ * HID];
__device__ fp16 g_wk[(size_t)HID * DKV];
__device__ fp16 g_wv[(size_t)HID * DKV];

__device__ float2 g_rope[(size_t)NTOK * 32];

// ---------------------------------------------------------------------------
__device__ __forceinline__ uint32_t smem_u32(const void* p) {
    uint32_t a;
    asm("{ .reg .u64 t; cvta.to.shared.u64 t, %1; cvt.u32.u64 %0, t; }"
        : "=r"(a) : "l"(p));
    return a;
}

#define CP16(dst, src) \
    asm volatile("cp.async.cg.shared.global [%0], [%1], 16;" \
        :: "r"(dst), "l"(src) : "memory")
#define CP_COMMIT() asm volatile("cp.async.commit_group;" ::: "memory")
#define CP_WAIT(n) asm volatile("cp.async.wait_group %0;" :: "n"(n) : "memory")

#define MMA16816(d, a, b0, b1) \
    asm volatile("mma.sync.aligned.m16n8k16.row.col.f32.f16.f16.f32 " \
        "{%0,%1,%2,%3}, {%4,%5,%6,%7}, {%8,%9}, {%0,%1,%2,%3};" \
        : "+f"((d)[0]), "+f"((d)[1]), "+f"((d)[2]), "+f"((d)[3]) \
        : "r"((a)[0]), "r"((a)[1]), "r"((a)[2]), "r"((a)[3]), "r"(b0), "r"(b1))

#define LDSM_4(r0, r1, r2, r3, a) \
    asm volatile("ldmatrix.sync.aligned.m8n8.x4.shared.b16 {%0,%1,%2,%3}, [%4];" \
        : "=r"(r0), "=r"(r1), "=r"(r2), "=r"(r3) : "r"(a))

#define LDSM_T4(r0, r1, r2, r3, a) \
    asm volatile("ldmatrix.sync.aligned.m8n8.x4.trans.shared.b16 {%0,%1,%2,%3}, [%4];" \
        : "=r"(r0), "=r"(r1), "=r"(r2), "=r"(r3) : "r"(a))

__device__ __forceinline__ uint32_t pack_half2(float a, float b) {
    __half2 h = __floats2half2_rn(a, b);
    return *reinterpret_cast<uint32_t*>(&h);
}

// ---------------------------------------------------------------------------
// Prep: coalesced fp32->fp16 converts (8 floats/thread) + RoPE table.
// (o_proj_w conversion lives in the attention launch's tail CTAs.)
// ---------------------------------------------------------------------------
__device__ __forceinline__ void conv8(const float* __restrict__ X,
                                      fp16* __restrict__ H, int i) {
    float4 v0 = reinterpret_cast<const float4*>(X)[2 * i];
    float4 v1 = reinterpret_cast<const float4*>(X)[2 * i + 1];
    uint4 o;
    o.x = pack_half2(v0.x, v0.y);
    o.y = pack_half2(v0.z, v0.w);
    o.z = pack_half2(v1.x, v1.y);
    o.w = pack_half2(v1.z, v1.w);
    reinterpret_cast<uint4*>(H)[i] = o;
}

#define PB_Q 8192
#define PB_K 512
#define PB_V 512
#define PB_H 2048
#define PB_R 256
#define PREP_BLOCKS (PB_Q + PB_K + PB_V + PB_H + PB_R)

__global__ void __launch_bounds__(256) prep_split(
    const float* __restrict__ q_proj_w,
    const float* __restrict__ k_w, const float* __restrict__ v_w,
    const float* __restrict__ hidden, const int* __restrict__ pos,
    fp16* __restrict__ wq,
    fp16* __restrict__ wk, fp16* __restrict__ wv,
    fp16* __restrict__ h, float2* __restrict__ rope)
{
    int b = blockIdx.x;
    int tid = threadIdx.x;
    if (b < PB_Q) {
        conv8(q_proj_w, wq, b * 256 + tid);
    } else if (b < PB_Q + PB_K) {
        conv8(k_w, wk, (b - PB_Q) * 256 + tid);
    } else if (b < PB_Q + PB_K + PB_V) {
        conv8(v_w, wv, (b - PB_Q - PB_K) * 256 + tid);
    } else if (b < PB_Q + PB_K + PB_V + PB_H) {
        conv8(hidden, h, (b - PB_Q - PB_K - PB_V) * 256 + tid);
    } else {
        int i = (b - PB_Q - PB_K - PB_V - PB_H) * 256 + tid;
        int t = i >> 5;
        int c = i & 31;
        float inv = powf(10000.0f, -(float)c * (1.0f / 32.0f));
        float s, cs;
        sincosf((float)pos[t] * inv, &s, &cs);
        rope[i] = make_float2(cs, s);
    }
}

// ---------------------------------------------------------------------------
// fp16 mma.sync GEMM (128x128 CTA tile, 128 threads, 4 warps of 64x64).
// 3-slot cp.async pipeline, one barrier per k-iteration.
// B from [K][N] via ldmatrix.trans.
// ---------------------------------------------------------------------------
#define LDA 40
#define LDB 136
#define A_E (128 * LDA)                // 5120 elements
#define B_E (32 * LDB)                 // 4352 elements
#define STAGE_EL (A_E + B_E)           // 9472 el = 18944 B
#define NSTG 3
#define GEMM_SMEM (1024 + NSTG * STAGE_EL * 2)   // 57856

__device__ __forceinline__ void issue_tile(
    uint32_t sB, int s, int kb,
    const fp16* __restrict__ Ag, const fp16* __restrict__ Bg,
    const int* __restrict__ rows, int n0, int K, int Nd, int tid)
{
#pragma unroll
    for (int rep = 0; rep < 4; rep++) {
        int f = tid + rep * 128;               // 0..511
        int m = f >> 2;
        int q = f & 3;
        uint32_t adst = sB + (uint32_t)s * (STAGE_EL * 2) + m * (LDA * 2) + q * 16;
        CP16(adst, Ag + (size_t)rows[m] * K + kb + q * 8);
        int kk = f >> 4;
        int seg = f & 15;
        uint32_t bdst = sB + (uint32_t)s * (STAGE_EL * 2) + (A_E + kk * LDB) * 2
                      + seg * 16;
        CP16(bdst, Bg + (size_t)(kb + kk) * Nd + n0 + seg * 8);
    }
}

__device__ __forceinline__ void gemm_mainloop(
    const fp16* __restrict__ Ag, const fp16* __restrict__ Bg,
    const int* __restrict__ idx,
    int K, int Nd, int m0, int n0, int zchunk, char* smc,
    float acc[4][8][4])
{
    int* rows = (int*)smc;
    const uint32_t sB = smem_u32(smc + 1024);
    const int tid = threadIdx.x;
    const int wid = tid >> 5;
    const int lane = tid & 31;

    {
        int lr = zchunk + m0 + tid;
        rows[tid] = idx ? idx[lr] : lr;
    }
    __syncthreads();

    const int wm = (wid & 1) * 64;
    const int wn = (wid >> 1) * 64;
    const uint32_t lnA = ((((lane >> 3) & 1) * 8 + (lane & 7)) * LDA + (lane >> 4) * 8) * 2;
    const uint32_t lnBT = ((lane & 15) * LDB + (lane >> 4) * 8) * 2;

#pragma unroll
    for (int a = 0; a < 4; a++)
#pragma unroll
        for (int b = 0; b < 8; b++)
#pragma unroll
            for (int c = 0; c < 4; c++) acc[a][b][c] = 0.f;

    const int nkt = K / 32;
    issue_tile(sB, 0, 0, Ag, Bg, rows, n0, K, Nd, tid); CP_COMMIT();
    issue_tile(sB, 1, 32, Ag, Bg, rows, n0, K, Nd, tid); CP_COMMIT();

    int s = 0;
    for (int kt = 0; kt < nkt; kt++) {
        if (kt < nkt - 1) CP_WAIT(1);
        else              CP_WAIT(0);
        __syncthreads();

        if (kt + 2 < nkt) {
            int s2 = (s + 2 >= NSTG) ? s + 2 - NSTG : s + 2;
            issue_tile(sB, s2, (kt + 2) * 32, Ag, Bg, rows, n0, K, Nd, tid);
            CP_COMMIT();
        }

        const uint32_t sb_s = sB + (uint32_t)s * (STAGE_EL * 2);
        const uint32_t bb_s = sb_s + (uint32_t)A_E * 2;

#pragma unroll
        for (int ks = 0; ks < 32; ks += 16) {
            uint32_t ah[4][4];
            uint32_t abase = sb_s + (uint32_t)(wm * LDA + ks) * 2 + lnA;
#pragma unroll
            for (int mi = 0; mi < 4; mi++)
                LDSM_4(ah[mi][0], ah[mi][1], ah[mi][2], ah[mi][3],
                       abase + mi * (16 * LDA * 2));
#pragma unroll
            for (int np = 0; np < 4; np++) {
                uint32_t boff = bb_s + (uint32_t)(ks * LDB + wn + np * 16) * 2 + lnBT;
                uint32_t b0, b1, b2, b3;
                LDSM_T4(b0, b1, b2, b3, boff);
#pragma unroll
                for (int mi = 0; mi < 4; mi++) {
                    MMA16816(acc[mi][2 * np], ah[mi], b0, b1);
                    MMA16816(acc[mi][2 * np + 1], ah[mi], b2, b3);
                }
            }
        }
        s = (s + 1 == NSTG) ? 0 : s + 1;
    }
}

// Epilogue: fused RMSNorm + NeoX RoPE (table) + fp16 convert (warp owns 64 cols = 1 head)
__device__ __forceinline__ void epi_norm_rope(
    float acc[4][8][4], const int* __restrict__ rows,
    const float* __restrict__ w, const float2* __restrict__ rope, float sc,
    fp16* __restrict__ Out, int outstride, int headcol0)
{
    const int lane = threadIdx.x & 31;
    const int wid = threadIdx.x >> 5;
    const int wm = (wid & 1) * 64;
    const int rq = lane >> 2, cq = lane & 3;

#pragma unroll
    for (int mi = 0; mi < 4; mi++) {
#pragma unroll
        for (int hf = 0; hf < 2; hf++) {
            int r = wm + mi * 16 + rq + hf * 8;
            int gr = rows[r];
            float ss = 0.f;
#pragma unroll
            for (int nf = 0; nf < 8; nf++) {
                float a = acc[mi][nf][hf * 2], b = acc[mi][nf][hf * 2 + 1];
                ss += a * a + b * b;
            }
            ss += __shfl_xor_sync(0xffffffff, ss, 1);
            ss += __shfl_xor_sync(0xffffffff, ss, 2);
            float rn = rsqrtf(ss * (1.0f / 64.0f) + 1e-6f) * sc;
            const float2* rt = rope + (size_t)gr * 32;
#pragma unroll
            for (int nf = 0; nf < 4; nf++) {
                float o1[2], o2[2];
#pragma unroll
                for (int par = 0; par < 2; par++) {
                    int c = nf * 8 + cq * 2 + par;
                    float y1 = acc[mi][nf][hf * 2 + par] * rn * w[c];
                    float y2 = acc[mi][nf + 4][hf * 2 + par] * rn * w[c + 32];
                    float2 cs = rt[c];
                    o1[par] = y1 * cs.x - y2 * cs.y;
                    o2[par] = y2 * cs.x + y1 * cs.y;
                }
                size_t base = (size_t)gr * outstride + headcol0 + nf * 8 + cq * 2;
                *reinterpret_cast<uint32_t*>(Out + base) = pack_half2(o1[0], o1[1]);
                *reinterpret_cast<uint32_t*>(Out + base + 32) = pack_half2(o2[0], o2[1]);
            }
        }
    }
}

// Epilogue: plain fp16 convert (v)
__device__ __forceinline__ void epi_conv(
    float acc[4][8][4], const int* __restrict__ rows,
    fp16* __restrict__ Out, int outstride, int col0)
{
    const int lane = threadIdx.x & 31;
    const int wid = threadIdx.x >> 5;
    const int wm = (wid & 1) * 64;
    const int wn = (wid >> 1) * 64;
    const int rq = lane >> 2, cq = lane & 3;
#pragma unroll
    for (int mi = 0; mi < 4; mi++) {
        int r = wm + mi * 16 + rq;
        size_t gr0 = (size_t)rows[r];
        size_t gr1 = (size_t)rows[r + 8];
#pragma unroll
        for (int nf = 0; nf < 8; nf++) {
            int col = col0 + wn + nf * 8 + cq * 2;
            *reinterpret_cast<uint32_t*>(Out + gr0 * outstride + col) =
                pack_half2(acc[mi][nf][0], acc[mi][nf][1]);
            *reinterpret_cast<uint32_t*>(Out + gr1 * outstride + col) =
                pack_half2(acc[mi][nf][2], acc[mi][nf][3]);
        }
    }
}

// Merged q-proj (bid<256, routed) + k-proj + v-proj; fused norm/rope epilogues.
__global__ void __launch_bounds__(128, 3) gemm_qkv(
    const fp16* __restrict__ h, const fp16* __restrict__ wq,
    const fp16* __restrict__ wk, const fp16* __restrict__ wv,
    const int* __restrict__ sort_idx, const float2* __restrict__ rope,
    const float* __restrict__ q_norm_w, const float* __restrict__ k_norm_w,
    fp16* __restrict__ qv, fp16* __restrict__ kv, fp16* __restrict__ vv)
{
    extern __shared__ char smc[];
    float acc[4][8][4];
    int* rows = (int*)smc;
    int bid = blockIdx.x;
    const int wn = ((threadIdx.x >> 5) >> 1) * 64;

    if (bid < 256) {
        int x = bid & 15, y = (bid >> 4) & 3, z = bid >> 6;
        gemm_mainloop(h, wq + (size_t)z * HID * DQ,
                      sort_idx, HID, DQ, y * 128, x * 128, z * CHUNK, smc, acc);
        epi_norm_rope(acc, rows, q_norm_w, rope, 0.125f, qv, DQ, x * 128 + wn);
    } else {
        int bb = bid - 256;
        int x = bb & 7, y = bb >> 3;
        if (x < 4) {
            gemm_mainloop(h, wk, nullptr, HID, DKV, y * 128, x * 128, 0, smc, acc);
            epi_norm_rope(acc, rows, k_norm_w, rope, 1.0f, kv, DKV, x * 128 + wn);
        } else {
            gemm_mainloop(h, wv, nullptr, HID, DKV, y * 128, (x - 4) * 128, 0, smc, acc);
            epi_conv(acc, rows, vv, DKV, (x - 4) * 128);
        }
    }
}

// o-proj (routed), fp32 output (R14 shape: 256 CTAs x 128 threads)
__global__ void __launch_bounds__(128, 3) gemm_o(
    const fp16* __restrict__ o, const fp16* __restrict__ wo,
    float* __restrict__ out, const int* __restrict__ sort_idx)
{
    extern __shared__ char smc[];
    float acc[4][8][4];
    int* rows = (int*)smc;
    int bid = blockIdx.x;
    int x = bid & 15, y = (bid >> 4) & 3, z = bid >> 6;
    gemm_mainloop(o, wo + (size_t)z * DQ * HID,
                  sort_idx, DQ, HID, y * 128, x * 128, z * CHUNK, smc, acc);

    const int lane = threadIdx.x & 31;
    const int wid = threadIdx.x >> 5;
    const int wm = (wid & 1) * 64;
    const int wn = (wid >> 1) * 64;
    const int rq = lane >> 2;
    const int cq = (lane & 3) * 2;
#pragma unroll
    for (int mi = 0; mi < 4; mi++) {
        int r = wm + mi * 16 + rq;
        size_t gr0 = (size_t)rows[r];
        size_t gr1 = (size_t)rows[r + 8];
#pragma unroll
        for (int ni = 0; ni < 8; ni++) {
            int col = x * 128 + wn + ni * 8 + cq;
            *reinterpret_cast<float2*>(&out[gr0 * HID + col]) =
                make_float2(acc[mi][ni][0], acc[mi][ni][1]);
            *reinterpret_cast<float2*>(&out[gr1 * HID + col]) =
                make_float2(acc[mi][ni][2], acc[mi][ni][3]);
        }
    }
}

// ---------------------------------------------------------------------------
// fp16 flash attention, AQ=64 / 128 threads / 3 CTAs per SM.
// 3-slot KV pipeline, one barrier per tile.
// Flattened 1D grid: first 1024 CTAs = attention (heavy-first),
// trailing CONV_CTAS convert o_proj_w fp32->fp16 (fills the drain tail).
// ---------------------------------------------------------------------------
#define AQ 64
#define AK 64
#define LDK 72
#define KSM (AK * LDK)     // 4608 elements
#define ASTG 3
#define ASMEM (2 * ASTG * KSM * 2 + ASTG * AK * 4)   // 56064
#define ATTN_CTAS ((NTOK / AQ) * NH)   // 1024
#define CONV_CTAS 4096                 // 4096 x (128 thr x 32 floats) = 16M floats

__device__ __forceinline__ void attn_issue(
    uint32_t sbase, int s, int kt, int kvh, int tid,
    const fp16* __restrict__ k_g, const fp16* __restrict__ v_g,
    const int* __restrict__ pos, int* __restrict__ kpos_sm)
{
#pragma unroll
    for (int i = 0; i < 8; i++) {
        int f = tid + i * 128;          // 0..1023
        int arr = f >> 9;               // 0=K, 1=V
        int r = (f >> 3) & 63;
        int seg = f & 7;
        const fp16* src = arr ? v_g : k_g;
        uint32_t dst = sbase + (uint32_t)((s * 2 + arr) * KSM + r * LDK) * 2
                     + seg * 16;
        CP16(dst, src + (size_t)(kt * AK + r) * DKV + (size_t)kvh * HD + seg * 8);
    }
    if (tid < AK) kpos_sm[s * AK + tid] = pos[kt * AK + tid];
    CP_COMMIT();
}

__global__ void __launch_bounds__(128, 3) attn_mma(
    const fp16* __restrict__ q_g, const fp16* __restrict__ k_g,
    const fp16* __restrict__ v_g, const int* __restrict__ pos,
    fp16* __restrict__ o_g,
    const float* __restrict__ o_proj_w, fp16* __restrict__ wo)
{
    extern __shared__ char sm[];
    const int tid = threadIdx.x;
    const int bidx = blockIdx.x;

    // ---- trailing converter CTAs: o_proj_w fp32 -> fp16 ----
    if (bidx >= ATTN_CTAS) {
        int cb = bidx - ATTN_CTAS;      // 0..CONV_CTAS-1
#pragma unroll
        for (int rep = 0; rep < 4; rep++)
            conv8(o_proj_w, wo, cb * 512 + rep * 128 + tid);
        return;
    }

    const uint32_t sbase = smem_u32(sm);
    int* kpos = (int*)(sm + (size_t)2 * ASTG * KSM * 2);

    const int w = tid >> 5;
    const int l = tid & 31;
    const int h = bidx & 31;
    const int qt = (NTOK / AQ) - 1 - (bidx >> 5);   // heavy tiles first
    const int kvh = h >> 2;
    const int q0 = qt * AQ;
    const int ntile = qt + 1;

    attn_issue(sbase, 0, 0, kvh, tid, k_g, v_g, pos, kpos);
    attn_issue(sbase, 1, 1 < ntile ? 1 : 0, kvh, tid, k_g, v_g, pos, kpos);

    const int rq = l >> 2;
    const int cq = l & 3;
    const int row0 = w * 16 + rq;

    uint32_t qf[4][4];
    {
        const fp16* qb = q_g + (size_t)(q0 + row0) * DQ + h * HD;
#pragma unroll
        for (int kf = 0; kf < 4; kf++) {
            int e0 = kf * 16 + cq * 2;
            qf[kf][0] = *reinterpret_cast<const uint32_t*>(qb + e0);
            qf[kf][1] = *reinterpret_cast<const uint32_t*>(qb + 8 * DQ + e0);
            qf[kf][2] = *reinterpret_cast<const uint32_t*>(qb + e0 + 8);
            qf[kf][3] = *reinterpret_cast<const uint32_t*>(qb + 8 * DQ + e0 + 8);
        }
    }
    const int qp0 = pos[q0 + row0];
    const int qp1 = pos[q0 + row0 + 8];

    float o[8][4];
#pragma unroll
    for (int nf = 0; nf < 8; nf++)
#pragma unroll
        for (int e = 0; e < 4; e++) o[nf][e] = 0.f;
    float m0 = -1e30f, m1 = -1e30f, l0 = 0.f, l1 = 0.f;

    const int lrow16 = l & 15;
    const int lsel = l >> 4;
    const uint32_t lnK = (((l >> 4) * 8 + (l & 7)) * LDK + ((l >> 3) & 1) * 8) * 2;

    int s = 0;
    for (int kt = 0; kt < ntile; kt++) {
        if (kt < ntile - 1) CP_WAIT(1);
        else                CP_WAIT(0);
        __syncthreads();

        if (kt + 2 < ntile) {
            int s2 = (s + 2 >= ASTG) ? s + 2 - ASTG : s + 2;
            attn_issue(sbase, s2, kt + 2, kvh, tid, k_g, v_g, pos, kpos);
        }

        const uint32_t kb = sbase + (uint32_t)((s * 2 + 0) * KSM) * 2;
        const uint32_t vb = sbase + (uint32_t)((s * 2 + 1) * KSM) * 2;

        float sv[8][4];
#pragma unroll
        for (int nf = 0; nf < 8; nf++)
#pragma unroll
            for (int e = 0; e < 4; e++) sv[nf][e] = 0.f;

#pragma unroll
        for (int kf = 0; kf < 4; kf++) {
#pragma unroll
            for (int np = 0; np < 4; np++) {
                uint32_t koff = kb + (uint32_t)(np * 16 * LDK) * 2 + kf * 32 + lnK;
                uint32_t b0, b1, b2, b3;
                LDSM_4(b0, b1, b2, b3, koff);
                MMA16816(sv[2 * np], qf[kf], b0, b1);
                MMA16816(sv[2 * np + 1], qf[kf], b2, b3);
            }
        }

        if (kt == qt) {
            const int* kp = kpos + s * AK;
#pragma unroll
            for (int nf = 0; nf < 8; nf++) {
                int c = nf * 8 + cq * 2;
                int k0 = kp[c], k1 = kp[c + 1];
                if (k0 > qp0) sv[nf][0] = -1e30f;
                if (k1 > qp0) sv[nf][1] = -1e30f;
                if (k0 > qp1) sv[nf][2] = -1e30f;
                if (k1 > qp1) sv[nf][3] = -1e30f;
            }
        }

        float mt0 = -1e30f, mt1 = -1e30f;
#pragma unroll
        for (int nf = 0; nf < 8; nf++) {
            mt0 = fmaxf(mt0, fmaxf(sv[nf][0], sv[nf][1]));
            mt1 = fmaxf(mt1, fmaxf(sv[nf][2], sv[nf][3]));
        }
        mt0 = fmaxf(mt0, __shfl_xor_sync(0xffffffff, mt0, 1));
        mt0 = fmaxf(mt0, __shfl_xor_sync(0xffffffff, mt0, 2));
        mt1 = fmaxf(mt1, __shfl_xor_sync(0xffffffff, mt1, 1));
        mt1 = fmaxf(mt1, __shfl_xor_sync(0xffffffff, mt1, 2));
        float mn0 = fmaxf(m0, mt0), mn1 = fmaxf(m1, mt1);
        float a0 = __expf(m0 - mn0), a1 = __expf(m1 - mn1);
        m0 = mn0; m1 = mn1;
#pragma unroll
        for (int nf = 0; nf < 8; nf++) {
            o[nf][0] *= a0; o[nf][1] *= a0;
            o[nf][2] *= a1; o[nf][3] *= a1;
        }
        float rs0 = 0.f, rs1 = 0.f;
#pragma unroll
        for (int nf = 0; nf < 8; nf++) {
            sv[nf][0] = __expf(sv[nf][0] - mn0); rs0 += sv[nf][0];
            sv[nf][1] = __expf(sv[nf][1] - mn0); rs0 += sv[nf][1];
            sv[nf][2] = __expf(sv[nf][2] - mn1); rs1 += sv[nf][2];
            sv[nf][3] = __expf(sv[nf][3] - mn1); rs1 += sv[nf][3];
        }
        rs0 += __shfl_xor_sync(0xffffffff, rs0, 1);
        rs0 += __shfl_xor_sync(0xffffffff, rs0, 2);
        rs1 += __shfl_xor_sync(0xffffffff, rs1, 1);
        rs1 += __shfl_xor_sync(0xffffffff, rs1, 2);
        l0 = l0 * a0 + rs0;
        l1 = l1 * a1 + rs1;

#pragma unroll
        for (int kfk = 0; kfk < 4; kfk++) {
            uint32_t pa[4];
            pa[0] = pack_half2(sv[2 * kfk][0], sv[2 * kfk][1]);
            pa[1] = pack_half2(sv[2 * kfk][2], sv[2 * kfk][3]);
            pa[2] = pack_half2(sv[2 * kfk + 1][0], sv[2 * kfk + 1][1]);
            pa[3] = pack_half2(sv[2 * kfk + 1][2], sv[2 * kfk + 1][3]);

            uint32_t vf[8][2];
#pragma unroll
            for (int nfp = 0; nfp < 4; nfp++) {
                uint32_t off = (uint32_t)((kfk * 16 + lrow16) * LDK
                                          + nfp * 16 + lsel * 8) * 2;
                uint32_t r0, r1, r2, r3;
                LDSM_T4(r0, r1, r2, r3, vb + off);
                vf[2 * nfp][0] = r0;     vf[2 * nfp][1] = r1;
                vf[2 * nfp + 1][0] = r2; vf[2 * nfp + 1][1] = r3;
            }
#pragma unroll
            for (int nf = 0; nf < 8; nf++)
                MMA16816(o[nf], pa, vf[nf][0], vf[nf][1]);
        }

        s = (s + 1 == ASTG) ? 0 : s + 1;
    }

    float i0 = 1.f / l0, i1 = 1.f / l1;
    int g0 = q0 + w * 16 + rq;
    int g1 = g0 + 8;
#pragma unroll
    for (int nf = 0; nf < 8; nf++) {
        int col = h * HD + nf * 8 + cq * 2;
        *reinterpret_cast<uint32_t*>(o_g + (size_t)g0 * DQ + col) =
            pack_half2(o[nf][0] * i0, o[nf][1] * i0);
        *reinterpret_cast<uint32_t*>(o_g + (size_t)g1 * DQ + col) =
            pack_half2(o[nf][2] * i1, o[nf][3] * i1);
    }
}

// ---------------------------------------------------------------------------
extern "C" void kernel_launch(void* const* d_in, const int* in_sizes, int n_in,
                              void* d_out, int out_size)
{
    const float* hidden    = (const float*)d_in[0];
    const int*   positions = (const int*)  d_in[1];
    const int*   sort_idx  = (const int*)  d_in[2];
    const float* q_proj_w  = (const float*)d_in[3];
    const float* o_proj_w  = (const float*)d_in[4];
    const float* k_w       = (const float*)d_in[5];
    const float* v_w       = (const float*)d_in[6];
    const float* q_norm_w  = (const float*)d_in[7];
    const float* k_norm_w  = (const float*)d_in[8];
    float* out = (float*)d_out;

    fp16 *h, *o, *qv, *kv, *vv, *wq, *wo, *wk, *wv;
    float2* rope;
    cudaGetSymbolAddress((void**)&h, g_h);
    cudaGetSymbolAddress((void**)&o, g_o);
    cudaGetSymbolAddress((void**)&qv, g_qv);
    cudaGetSymbolAddress((void**)&kv, g_kv);
    cudaGetSymbolAddress((void**)&vv, g_vv);
    cudaGetSymbolAddress((void**)&wq, g_wq);
    cudaGetSymbolAddress((void**)&wo, g_wo);
    cudaGetSymbolAddress((void**)&wk, g_wk);
    cudaGetSymbolAddress((void**)&wv, g_wv);
    cudaGetSymbolAddress((void**)&rope, g_rope);

    cudaFuncSetAttribute(gemm_qkv, cudaFuncAttributeMaxDynamicSharedMemorySize, GEMM_SMEM);
    cudaFuncSetAttribute(gemm_o, cudaFuncAttributeMaxDynamicSharedMemorySize, GEMM_SMEM);
    cudaFuncSetAttribute(attn_mma, cudaFuncAttributeMaxDynamicSharedMemorySize, ASMEM);

    // 1) converts (wq/wk/wv/hidden) + RoPE table (wo converts in attn tail)
    prep_split<<<PREP_BLOCKS, 256>>>(
        q_proj_w, k_w, v_w, hidden, positions, wq, wk, wv, h, rope);

    // 2) q/k/v projections
    gemm_qkv<<<384, 128, GEMM_SMEM>>>(
        h, wq, wk, wv, sort_idx, rope, q_norm_w, k_norm_w, qv, kv, vv);

    // 3) flash attention + trailing wo-converter CTAs
    attn_mma<<<ATTN_CTAS + CONV_CTAS, 128, ASMEM>>>(
        qv, kv, vv, positions, o, o_proj_w, wo);

    // 4) o-proj (routed)
    gemm_o<<<256, 128, GEMM_SMEM>>>(o, wo, out, sort_idx);
}